// round 16
// baseline (speedup 1.0000x reference)
#include <cuda_runtime.h>
#include <cuda_fp16.h>
#include <math.h>
#include <stdint.h>

// ---------------- problem constants ----------------
#define B_    2048
#define DR_   1024
#define DI_   1024
#define DO_   1024
#define E_    8
#define TOPK_ 2
#define H1_   2048
#define H2_   2048
#define NS_   (B_ * TOPK_)
#define TILE_ 128
#define MAXROWS_ (NS_ + E_ * TILE_)   // 5120
#define MAXTILES_ (MAXROWS_ / TILE_)  // 40

// ---------------- device scratch ----------------
__device__ float g_or[MAXROWS_ * (size_t)DO_];
__device__ int   g_perm[MAXROWS_];
__device__ int   g_inv[NS_];
__device__ float g_gw[NS_];
__device__ int   g_idx[NS_];
__device__ int   g_count[E_];
__device__ int   g_cursor[E_];
__device__ int   g_base[E_];
__device__ int   g_tile_e[MAXTILES_];

// fp16 weights, K-major (same layout as source): [e][K][N]
__device__ __half g_w1[(size_t)E_ * DI_ * H1_];
__device__ __half g_w2[(size_t)E_ * H1_ * H2_];
__device__ __half g_w3[(size_t)E_ * H2_ * DO_];

// fp16 activations
__device__ __half g_x[(size_t)B_ * DI_];
__device__ __half g_a1[MAXROWS_ * (size_t)H1_];
__device__ __half g_a2[MAXROWS_ * (size_t)H2_];

// ---------------- PTX helpers ----------------
__device__ __forceinline__ uint32_t smem_u32(const void* p) {
    uint32_t a;
    asm("{ .reg .u64 t; cvta.to.shared.u64 t, %1; cvt.u32.u64 %0, t; }" : "=r"(a) : "l"(p));
    return a;
}
#define CP16(dst, src) \
    asm volatile("cp.async.cg.shared.global [%0], [%1], 16;" :: "r"(dst), "l"(src))
#define CP16Z(dst, src, n) \
    asm volatile("cp.async.cg.shared.global [%0], [%1], 16, %2;" :: "r"(dst), "l"(src), "r"(n))
#define CP_COMMIT() asm volatile("cp.async.commit_group;" ::: "memory")
#define CP_WAIT2()  asm volatile("cp.async.wait_group 2;" ::: "memory")

__device__ __forceinline__ void ldm_x4(uint32_t* r, uint32_t addr) {
    asm volatile("ldmatrix.sync.aligned.m8n8.x4.shared.b16 {%0,%1,%2,%3}, [%4];"
                 : "=r"(r[0]), "=r"(r[1]), "=r"(r[2]), "=r"(r[3]) : "r"(addr));
}
__device__ __forceinline__ uint32_t movm_t(uint32_t s) {
    uint32_t d;
    asm volatile("movmatrix.sync.aligned.m8n8.trans.b16 %0, %1;" : "=r"(d) : "r"(s));
    return d;
}
__device__ __forceinline__ void mma16816(float* d, const uint32_t* a, uint32_t b0, uint32_t b1) {
    asm volatile(
        "mma.sync.aligned.m16n8k16.row.col.f32.f16.f16.f32 "
        "{%0,%1,%2,%3}, {%4,%5,%6,%7}, {%8,%9}, {%0,%1,%2,%3};"
        : "+f"(d[0]), "+f"(d[1]), "+f"(d[2]), "+f"(d[3])
        : "r"(a[0]), "r"(a[1]), "r"(a[2]), "r"(a[3]), "r"(b0), "r"(b1));
}
__device__ __forceinline__ void cvt8(const float* src, __half* dst) {
    float4 v0 = *(const float4*)(src);
    float4 v1 = *(const float4*)(src + 4);
    __half2 h0 = __floats2half2_rn(v0.x, v0.y);
    __half2 h1 = __floats2half2_rn(v0.z, v0.w);
    __half2 h2 = __floats2half2_rn(v1.x, v1.y);
    __half2 h3 = __floats2half2_rn(v1.z, v1.w);
    *(uint4*)(dst) = make_uint4(*(uint32_t*)&h0, *(uint32_t*)&h1,
                                *(uint32_t*)&h2, *(uint32_t*)&h3);
}

// ---------------- init / router / prefix / scatter ----------------
__global__ void init_k() {
    int i = blockIdx.x * blockDim.x + threadIdx.x;
    if (i < E_) { g_count[i] = 0; g_cursor[i] = 0; }
    if (i < MAXTILES_) g_tile_e[i] = -1;
    if (i < MAXROWS_) g_perm[i] = -1;
}

__global__ void router_k(const float* __restrict__ xr, const float* __restrict__ Wg,
                         const float* __restrict__ bg, const float* __restrict__ eb) {
    int t = blockIdx.x, tid = threadIdx.x;
    const float* x = xr + (size_t)t * DR_;
    float acc[E_];
#pragma unroll
    for (int e = 0; e < E_; e++) acc[e] = 0.f;
    for (int d = tid; d < DR_; d += 256) {
        float xv = x[d];
        const float* w = Wg + (size_t)d * E_;
#pragma unroll
        for (int e = 0; e < E_; e++) acc[e] += xv * w[e];
    }
    __shared__ float red[E_][256];
#pragma unroll
    for (int e = 0; e < E_; e++) red[e][tid] = acc[e];
    __syncthreads();
    for (int s = 128; s > 0; s >>= 1) {
        if (tid < s)
#pragma unroll
            for (int e = 0; e < E_; e++) red[e][tid] += red[e][tid + s];
        __syncthreads();
    }
    if (tid == 0) {
        float gate[E_], sc[E_];
#pragma unroll
        for (int e = 0; e < E_; e++) { gate[e] = red[e][0] + bg[e]; sc[e] = gate[e] + eb[e]; }
        int i0 = 0;
        for (int e = 1; e < E_; e++) if (sc[e] > sc[i0]) i0 = e;
        int i1 = -1;
        for (int e = 0; e < E_; e++) {
            if (e == i0) continue;
            if (i1 < 0 || sc[e] > sc[i1]) i1 = e;
        }
        float r0 = gate[i0], r1 = gate[i1];
        float m = fmaxf(r0, r1);
        float e0 = expf(r0 - m), e1 = expf(r1 - m);
        float inv = 1.f / (e0 + e1);
        g_idx[t * 2] = i0; g_idx[t * 2 + 1] = i1;
        g_gw[t * 2] = e0 * inv; g_gw[t * 2 + 1] = e1 * inv;
        atomicAdd(&g_count[i0], 1);
        atomicAdd(&g_count[i1], 1);
    }
}

__global__ void prefix_k() {
    if (blockIdx.x == 0 && threadIdx.x == 0) {
        int row = 0, nt = 0;
        for (int e = 0; e < E_; e++) {
            g_base[e] = row;
            int tiles = (g_count[e] + TILE_ - 1) / TILE_;
            for (int k = 0; k < tiles; k++) g_tile_e[nt++] = e;
            row += tiles * TILE_;
        }
    }
}

__global__ void scatter_k() {
    int s = blockIdx.x * blockDim.x + threadIdx.x;
    if (s >= NS_) return;
    int e = g_idx[s];
    int pos = atomicAdd(&g_cursor[e], 1);
    int r = g_base[e] + pos;
    g_perm[r] = s;
    g_inv[s] = r;
}

// ---------------- streaming fp32 -> fp16 cvt (layer-1 weights only) ----------
__global__ void wcvt1_k(const float* __restrict__ W) {
    size_t i = ((size_t)blockIdx.x * 256 + threadIdx.x) * 8;
    cvt8(W + i, g_w1 + i);
}

// ---------------- x_expert fp32 -> fp16 ----------------
__global__ void xsplit_k(const float* __restrict__ x) {
    size_t i = ((size_t)blockIdx.x * 256 + threadIdx.x) * 4;
    float4 v = *(const float4*)(x + i);
    __half2 h0 = __floats2half2_rn(v.x, v.y);
    __half2 h1 = __floats2half2_rn(v.z, v.w);
    *(uint2*)(g_x + i) = make_uint2(*(uint32_t*)&h0, *(uint32_t*)&h1);
}

// ---------------- HMMA GEMM: 128x128 CTA, BK=32, 4-stage, K-major W ----
// + interleaved conversion of the NEXT layer's weights: each CTA owns a
//   deterministic slice; one 2048-elem block is converted per kc iteration
//   (independent work hiding in the MMA shadow). Empty-tile CTAs drain
//   their slice immediately (overlaps wave 1).
#define AROWB  80
#define WROWB  272
#define AREG   10240
#define STAGE  18944
#define NSTG   4
#define SMEM_GEMM (NSTG * STAGE)   // 75776 -> 2 CTAs/SM

template <int LAYER, int Kd, int Nd>
__global__ void __launch_bounds__(256, 2)
mma_gemm_k(const float* __restrict__ Ball, const float* __restrict__ Wnext) {
    extern __shared__ __align__(128) char smem[];

    int rt = blockIdx.y, ct = blockIdx.x;
    int e = g_tile_e[rt];
    int tid = threadIdx.x;

    // ---- interleaved-conversion slice setup ----
    constexpr size_t CVT_TOTAL =
        (LAYER == 1) ? (size_t)E_ * H1_ * H2_ :
        (LAYER == 2) ? (size_t)E_ * H2_ * DO_ : 1;
    constexpr int NCTA = (Nd / 128) * MAXTILES_;
    constexpr size_t NBLK = (CVT_TOTAL / 2048 + NCTA - 1) / NCTA;  // blocks/CTA
    __half* Wdst = (LAYER == 1) ? g_w2 : g_w3;
    size_t cvt_pos = 0, cvt_end = 0;
    if (LAYER < 3) {
        size_t ci = (size_t)rt * (Nd / 128) + ct;
        size_t lo = ci * NBLK * 2048;
        size_t hi = lo + NBLK * 2048;
        if (hi > CVT_TOTAL) hi = CVT_TOTAL;
        cvt_pos = lo + (size_t)tid * 8;
        cvt_end = hi;
    }

    if (e >= 0) {
        const __half *Wt, *Ain;
        if (LAYER == 1)      { Wt = g_w1; Ain = g_x;  }
        else if (LAYER == 2) { Wt = g_w2; Ain = g_a1; }
        else                 { Wt = g_w3; Ain = g_a2; }

        int row0 = rt * 128, col0 = ct * 128;
        const float* bias = Ball + (size_t)e * Nd;
        const __half* We = Wt + (size_t)e * Kd * Nd + col0;

        int wid = tid >> 5, lid = tid & 31;
        int g = lid >> 2, t = lid & 3;
        int wm = wid & 1, wn = wid >> 1;
        int m_base = wm * 64, n_base = wn * 32;

        int arow = tid >> 1, half = tid & 1;
        const __half* Ar;
        uint32_t asz = 16;
        if (LAYER == 1) {
            int slot = g_perm[row0 + arow];
            if (slot >= 0) Ar = Ain + (size_t)(slot >> 1) * Kd;
            else { Ar = Ain; asz = 0; }
        } else {
            Ar = Ain + (size_t)(row0 + arow) * Kd;
        }
        int wkrow = tid >> 3, wchunk = tid & 7;

        uint32_t sbase = smem_u32(smem);
        uint32_t afoff = (uint32_t)arow * AROWB + half * 32;
        uint32_t wfoff = AREG + (uint32_t)wkrow * WROWB + wchunk * 32;

        float acc[4][4][4];
#pragma unroll
        for (int mt = 0; mt < 4; mt++)
#pragma unroll
            for (int nt = 0; nt < 4; nt++)
#pragma unroll
                for (int q = 0; q < 4; q++) acc[mt][nt][q] = 0.f;

        constexpr int KC = Kd / 32;

        auto fill = [&](int kc) {
            uint32_t stg = sbase + (uint32_t)(kc & (NSTG - 1)) * STAGE;
            int k0 = kc * 32;
            const __half* sa = Ar + k0 + half * 16;
            CP16Z(stg + afoff, sa, asz); CP16Z(stg + afoff + 16, sa + 8, asz);
            const __half* sw = We + (size_t)(k0 + wkrow) * Nd + wchunk * 16;
            CP16(stg + wfoff, sw); CP16(stg + wfoff + 16, sw + 8);
        };

        fill(0); CP_COMMIT();
        fill(1); CP_COMMIT();
        fill(2); CP_COMMIT();

        uint32_t lrow = lid & 15;
        uint32_t lhalf16 = (lid >> 4) * 16;

        for (int kc = 0; kc < KC; kc++) {
            CP_WAIT2();
            __syncthreads();
            if (kc + 3 < KC) fill(kc + 3);
            CP_COMMIT();

            // interleaved conversion: one 2048-elem block per kc (independent)
            if (LAYER < 3 && cvt_pos < cvt_end) {
                cvt8(Wnext + cvt_pos, Wdst + cvt_pos);
                cvt_pos += 2048;
            }

            uint32_t stg = sbase + (uint32_t)(kc & (NSTG - 1)) * STAGE;
#pragma unroll
            for (int ks = 0; ks < 2; ks++) {
                uint32_t ah[4][4];
                uint32_t koff = (uint32_t)ks * 32 + lhalf16;
#pragma unroll
                for (int mt = 0; mt < 4; mt++)
                    ldm_x4(ah[mt], stg + (uint32_t)(m_base + mt * 16 + lrow) * AROWB + koff);

                uint32_t b0[4], b1[4];
#pragma unroll
                for (int nn = 0; nn < 2; nn++) {
                    uint32_t r[4];
                    uint32_t addr = stg + AREG
                                  + (uint32_t)(ks * 16 + lrow) * WROWB
                                  + (uint32_t)(n_base + nn * 16) * 2 + lhalf16;
                    ldm_x4(r, addr);
                    b0[2 * nn]     = movm_t(r[0]);
                    b1[2 * nn]     = movm_t(r[1]);
                    b0[2 * nn + 1] = movm_t(r[2]);
                    b1[2 * nn + 1] = movm_t(r[3]);
                }
#pragma unroll
                for (int mt = 0; mt < 4; mt++)
#pragma unroll
                    for (int nt = 0; nt < 4; nt++)
                        mma16816(acc[mt][nt], ah[mt], b0[nt], b1[nt]);
            }
        }

        // ---- epilogue ----
        __half* Oh = nullptr;
        if (LAYER == 1)      Oh = g_a1;
        else if (LAYER == 2) Oh = g_a2;

#pragma unroll
        for (int mt = 0; mt < 4; mt++) {
            int rA = row0 + m_base + mt * 16 + g;
#pragma unroll
            for (int nt = 0; nt < 4; nt++) {
                int col = col0 + n_base + nt * 8 + t * 2;
                float2 bv = *(const float2*)(bias + col);
                float2 o0, o1;
                o0.x = acc[mt][nt][0] + bv.x; o0.y = acc[mt][nt][1] + bv.y;
                o1.x = acc[mt][nt][2] + bv.x; o1.y = acc[mt][nt][3] + bv.y;
                if (LAYER < 3) {
                    o0.x = fmaxf(o0.x, 0.f); o0.y = fmaxf(o0.y, 0.f);
                    o1.x = fmaxf(o1.x, 0.f); o1.y = fmaxf(o1.y, 0.f);
                    __half2 h0 = __floats2half2_rn(o0.x, o0.y);
                    __half2 h1 = __floats2half2_rn(o1.x, o1.y);
                    *(uint32_t*)(Oh + (size_t)rA * Nd + col)       = *(uint32_t*)&h0;
                    *(uint32_t*)(Oh + (size_t)(rA + 8) * Nd + col) = *(uint32_t*)&h1;
                } else {
                    *(float2*)(g_or + (size_t)rA * Nd + col)       = o0;
                    *(float2*)(g_or + (size_t)(rA + 8) * Nd + col) = o1;
                }
            }
        }
    }

    // ---- drain any remaining conversion blocks (empty CTAs do all here) ----
    if (LAYER < 3) {
        while (cvt_pos < cvt_end) {
            cvt8(Wnext + cvt_pos, Wdst + cvt_pos);
            cvt_pos += 2048;
        }
    }
}

// ---------------- combine ----------------
__global__ void combine_k(float* __restrict__ out) {
    int t = blockIdx.x, c = threadIdx.x;
    int r0 = g_inv[t * 2], r1 = g_inv[t * 2 + 1];
    float w0 = g_gw[t * 2], w1 = g_gw[t * 2 + 1];
    const float4* a = (const float4*)(g_or + (size_t)r0 * DO_);
    const float4* b = (const float4*)(g_or + (size_t)r1 * DO_);
    float4 va = a[c], vb = b[c], o;
    o.x = w0 * va.x + w1 * vb.x;
    o.y = w0 * va.y + w1 * vb.y;
    o.z = w0 * va.z + w1 * vb.z;
    o.w = w0 * va.w + w1 * vb.w;
    ((float4*)(out + (size_t)t * DO_))[c] = o;
}

__global__ void idxout_k(float* __restrict__ dst, int n) {
    int i = blockIdx.x * blockDim.x + threadIdx.x;
    if (i < n) dst[i] = (float)g_idx[i];
}

// ---------------- launch ----------------
extern "C" void kernel_launch(void* const* d_in, const int* in_sizes, int n_in,
                              void* d_out, int out_size) {
    (void)in_sizes; (void)n_in;
    const float* xr = (const float*)d_in[0];
    const float* xe = (const float*)d_in[1];
    const float* Wg = (const float*)d_in[2];
    const float* bg = (const float*)d_in[3];
    const float* eb = (const float*)d_in[4];
    const float* W1 = (const float*)d_in[5];
    const float* b1 = (const float*)d_in[6];
    const float* W2 = (const float*)d_in[7];
    const float* b2 = (const float*)d_in[8];
    const float* W3 = (const float*)d_in[9];
    const float* b3 = (const float*)d_in[10];
    float* out = (float*)d_out;

    static cudaStream_t sB = 0;
    static cudaEvent_t evRoot = 0, ev_w1 = 0;
    if (sB == 0) {
        cudaStreamCreateWithFlags(&sB, cudaStreamNonBlocking);
        cudaEventCreateWithFlags(&evRoot, cudaEventDisableTiming);
        cudaEventCreateWithFlags(&ev_w1, cudaEventDisableTiming);
    }

    cudaFuncSetAttribute(mma_gemm_k<1, DI_, H1_>, cudaFuncAttributeMaxDynamicSharedMemorySize, SMEM_GEMM);
    cudaFuncSetAttribute(mma_gemm_k<2, H1_, H2_>, cudaFuncAttributeMaxDynamicSharedMemorySize, SMEM_GEMM);
    cudaFuncSetAttribute(mma_gemm_k<3, H2_, DO_>, cudaFuncAttributeMaxDynamicSharedMemorySize, SMEM_GEMM);

    // fork: wcvt1 overlaps the routing chain
    cudaEventRecord(evRoot, 0);
    cudaStreamWaitEvent(sB, evRoot, 0);
    wcvt1_k<<<(int)(((size_t)E_ * DI_ * H1_ / 8) / 256), 256, 0, sB>>>(W1);
    cudaEventRecord(ev_w1, sB);

    // origin: routing chain
    init_k<<<(MAXROWS_ + 255) / 256, 256>>>();
    router_k<<<B_, 256>>>(xr, Wg, bg, eb);
    xsplit_k<<<(B_ * DI_ / 4) / 256, 256>>>(xe);
    prefix_k<<<1, 1>>>();
    scatter_k<<<NS_ / 256, 256>>>();

    // join + GEMM chain; GEMM1 converts W2 inline, GEMM2 converts W3 inline
    cudaStreamWaitEvent(0, ev_w1, 0);
    mma_gemm_k<1, DI_, H1_><<<dim3(H1_ / 128, MAXTILES_), 256, SMEM_GEMM>>>(b1, W2);
    mma_gemm_k<2, H1_, H2_><<<dim3(H2_ / 128, MAXTILES_), 256, SMEM_GEMM>>>(b2, W3);
    mma_gemm_k<3, H2_, DO_><<<dim3(DO_ / 128, MAXTILES_), 256, SMEM_GEMM>>>(b3, nullptr);

    combine_k<<<B_, 256>>>(out);

    int tail = out_size - B_ * DO_;
    if (tail > 0) {
        int n = tail < NS_ ? tail : NS_;
        idxout_k<<<(n + 255) / 256, 256>>>(out + (size_t)B_ * DO_, n);
    }
}

// round 17
// speedup vs baseline: 1.0136x; 1.0136x over previous
#include <cuda_runtime.h>
#include <cuda_fp16.h>
#include <math.h>
#include <stdint.h>

// ---------------- problem constants ----------------
#define B_    2048
#define DR_   1024
#define DI_   1024
#define DO_   1024
#define E_    8
#define TOPK_ 2
#define H1_   2048
#define H2_   2048
#define NS_   (B_ * TOPK_)
#define TILE_ 128
#define MAXROWS_ (NS_ + E_ * TILE_)   // 5120
#define MAXTILES_ (MAXROWS_ / TILE_)  // 40

// ---------------- device scratch ----------------
__device__ float g_or[MAXROWS_ * (size_t)DO_];
__device__ int   g_perm[MAXROWS_];
__device__ int   g_inv[NS_];
__device__ float g_gw[NS_];
__device__ int   g_idx[NS_];
__device__ int   g_count[E_];
__device__ int   g_cursor[E_];
__device__ int   g_base[E_];
__device__ int   g_tile_e[MAXTILES_];

// fp16 weights, K-major (same layout as source): [e][K][N]
__device__ __half g_w1[(size_t)E_ * DI_ * H1_];
__device__ __half g_w2[(size_t)E_ * H1_ * H2_];
__device__ __half g_w3[(size_t)E_ * H2_ * DO_];

// fp16 activations
__device__ __half g_x[(size_t)B_ * DI_];
__device__ __half g_a1[MAXROWS_ * (size_t)H1_];
__device__ __half g_a2[MAXROWS_ * (size_t)H2_];

// ---------------- PTX helpers ----------------
__device__ __forceinline__ uint32_t smem_u32(const void* p) {
    uint32_t a;
    asm("{ .reg .u64 t; cvta.to.shared.u64 t, %1; cvt.u32.u64 %0, t; }" : "=r"(a) : "l"(p));
    return a;
}
#define CP16(dst, src) \
    asm volatile("cp.async.cg.shared.global [%0], [%1], 16;" :: "r"(dst), "l"(src))
#define CP16Z(dst, src, n) \
    asm volatile("cp.async.cg.shared.global [%0], [%1], 16, %2;" :: "r"(dst), "l"(src), "r"(n))
#define CP_COMMIT() asm volatile("cp.async.commit_group;" ::: "memory")
#define CP_WAIT2()  asm volatile("cp.async.wait_group 2;" ::: "memory")

__device__ __forceinline__ void ldm_x4(uint32_t* r, uint32_t addr) {
    asm volatile("ldmatrix.sync.aligned.m8n8.x4.shared.b16 {%0,%1,%2,%3}, [%4];"
                 : "=r"(r[0]), "=r"(r[1]), "=r"(r[2]), "=r"(r[3]) : "r"(addr));
}
__device__ __forceinline__ uint32_t movm_t(uint32_t s) {
    uint32_t d;
    asm volatile("movmatrix.sync.aligned.m8n8.trans.b16 %0, %1;" : "=r"(d) : "r"(s));
    return d;
}
__device__ __forceinline__ void mma16816(float* d, const uint32_t* a, uint32_t b0, uint32_t b1) {
    asm volatile(
        "mma.sync.aligned.m16n8k16.row.col.f32.f16.f16.f32 "
        "{%0,%1,%2,%3}, {%4,%5,%6,%7}, {%8,%9}, {%0,%1,%2,%3};"
        : "+f"(d[0]), "+f"(d[1]), "+f"(d[2]), "+f"(d[3])
        : "r"(a[0]), "r"(a[1]), "r"(a[2]), "r"(a[3]), "r"(b0), "r"(b1));
}
__device__ __forceinline__ void cvt8(const float* src, __half* dst) {
    float4 v0 = *(const float4*)(src);
    float4 v1 = *(const float4*)(src + 4);
    __half2 h0 = __floats2half2_rn(v0.x, v0.y);
    __half2 h1 = __floats2half2_rn(v0.z, v0.w);
    __half2 h2 = __floats2half2_rn(v1.x, v1.y);
    __half2 h3 = __floats2half2_rn(v1.z, v1.w);
    *(uint4*)(dst) = make_uint4(*(uint32_t*)&h0, *(uint32_t*)&h1,
                                *(uint32_t*)&h2, *(uint32_t*)&h3);
}
__device__ __forceinline__ void cvt8_store(float4 v0, float4 v1, __half* dst) {
    __half2 h0 = __floats2half2_rn(v0.x, v0.y);
    __half2 h1 = __floats2half2_rn(v0.z, v0.w);
    __half2 h2 = __floats2half2_rn(v1.x, v1.y);
    __half2 h3 = __floats2half2_rn(v1.z, v1.w);
    *(uint4*)(dst) = make_uint4(*(uint32_t*)&h0, *(uint32_t*)&h1,
                                *(uint32_t*)&h2, *(uint32_t*)&h3);
}

// ---------------- init / router / prefix / scatter ----------------
__global__ void init_k() {
    int i = blockIdx.x * blockDim.x + threadIdx.x;
    if (i < E_) { g_count[i] = 0; g_cursor[i] = 0; }
    if (i < MAXTILES_) g_tile_e[i] = -1;
    if (i < MAXROWS_) g_perm[i] = -1;
}

__global__ void router_k(const float* __restrict__ xr, const float* __restrict__ Wg,
                         const float* __restrict__ bg, const float* __restrict__ eb) {
    int t = blockIdx.x, tid = threadIdx.x;
    const float* x = xr + (size_t)t * DR_;
    float acc[E_];
#pragma unroll
    for (int e = 0; e < E_; e++) acc[e] = 0.f;
    for (int d = tid; d < DR_; d += 256) {
        float xv = x[d];
        const float* w = Wg + (size_t)d * E_;
#pragma unroll
        for (int e = 0; e < E_; e++) acc[e] += xv * w[e];
    }
    __shared__ float red[E_][256];
#pragma unroll
    for (int e = 0; e < E_; e++) red[e][tid] = acc[e];
    __syncthreads();
    for (int s = 128; s > 0; s >>= 1) {
        if (tid < s)
#pragma unroll
            for (int e = 0; e < E_; e++) red[e][tid] += red[e][tid + s];
        __syncthreads();
    }
    if (tid == 0) {
        float gate[E_], sc[E_];
#pragma unroll
        for (int e = 0; e < E_; e++) { gate[e] = red[e][0] + bg[e]; sc[e] = gate[e] + eb[e]; }
        int i0 = 0;
        for (int e = 1; e < E_; e++) if (sc[e] > sc[i0]) i0 = e;
        int i1 = -1;
        for (int e = 0; e < E_; e++) {
            if (e == i0) continue;
            if (i1 < 0 || sc[e] > sc[i1]) i1 = e;
        }
        float r0 = gate[i0], r1 = gate[i1];
        float m = fmaxf(r0, r1);
        float e0 = expf(r0 - m), e1 = expf(r1 - m);
        float inv = 1.f / (e0 + e1);
        g_idx[t * 2] = i0; g_idx[t * 2 + 1] = i1;
        g_gw[t * 2] = e0 * inv; g_gw[t * 2 + 1] = e1 * inv;
        atomicAdd(&g_count[i0], 1);
        atomicAdd(&g_count[i1], 1);
    }
}

__global__ void prefix_k() {
    if (blockIdx.x == 0 && threadIdx.x == 0) {
        int row = 0, nt = 0;
        for (int e = 0; e < E_; e++) {
            g_base[e] = row;
            int tiles = (g_count[e] + TILE_ - 1) / TILE_;
            for (int k = 0; k < tiles; k++) g_tile_e[nt++] = e;
            row += tiles * TILE_;
        }
    }
}

__global__ void scatter_k() {
    int s = blockIdx.x * blockDim.x + threadIdx.x;
    if (s >= NS_) return;
    int e = g_idx[s];
    int pos = atomicAdd(&g_cursor[e], 1);
    int r = g_base[e] + pos;
    g_perm[r] = s;
    g_inv[s] = r;
}

// ---------------- streaming fp32 -> fp16 cvt (layer-1 weights only) ----------
__global__ void wcvt1_k(const float* __restrict__ W) {
    size_t i = ((size_t)blockIdx.x * 256 + threadIdx.x) * 8;
    cvt8(W + i, g_w1 + i);
}

// ---------------- x_expert fp32 -> fp16 ----------------
__global__ void xsplit_k(const float* __restrict__ x) {
    size_t i = ((size_t)blockIdx.x * 256 + threadIdx.x) * 4;
    float4 v = *(const float4*)(x + i);
    __half2 h0 = __floats2half2_rn(v.x, v.y);
    __half2 h1 = __floats2half2_rn(v.z, v.w);
    *(uint2*)(g_x + i) = make_uint2(*(uint32_t*)&h0, *(uint32_t*)&h1);
}

// ---------------- HMMA GEMM: 128x128 CTA, BK=32, 4-stage, K-major W ----
// + interleaved conversion of the NEXT layer's weights, software-pipelined:
//   LDG at the top of each kc iteration, cvt+STG after the MMA block (the
//   ~1000-cycle MMA sequence hides the 577-cycle DRAM latency). Empty-tile
//   CTAs drain their slice in a plain streaming loop (overlaps wave 1).
#define AROWB  80
#define WROWB  272
#define AREG   10240
#define STAGE  18944
#define NSTG   4
#define SMEM_GEMM (NSTG * STAGE)   // 75776 -> 2 CTAs/SM

template <int LAYER, int Kd, int Nd>
__global__ void __launch_bounds__(256, 2)
mma_gemm_k(const float* __restrict__ Ball, const float* __restrict__ Wnext) {
    extern __shared__ __align__(128) char smem[];

    int rt = blockIdx.y, ct = blockIdx.x;
    int e = g_tile_e[rt];
    int tid = threadIdx.x;

    // ---- interleaved-conversion slice setup ----
    constexpr size_t CVT_TOTAL =
        (LAYER == 1) ? (size_t)E_ * H1_ * H2_ :
        (LAYER == 2) ? (size_t)E_ * H2_ * DO_ : 1;
    constexpr int NCTA = (Nd / 128) * MAXTILES_;
    constexpr size_t NBLK = (CVT_TOTAL / 2048 + NCTA - 1) / NCTA;  // blocks/CTA
    __half* Wdst = (LAYER == 1) ? g_w2 : g_w3;
    size_t cvt_pos = 0, cvt_end = 0;
    if (LAYER < 3) {
        size_t ci = (size_t)rt * (Nd / 128) + ct;
        size_t lo = ci * NBLK * 2048;
        size_t hi = lo + NBLK * 2048;
        if (hi > CVT_TOTAL) hi = CVT_TOTAL;
        cvt_pos = lo + (size_t)tid * 8;
        cvt_end = hi;
    }

    if (e >= 0) {
        const __half *Wt, *Ain;
        if (LAYER == 1)      { Wt = g_w1; Ain = g_x;  }
        else if (LAYER == 2) { Wt = g_w2; Ain = g_a1; }
        else                 { Wt = g_w3; Ain = g_a2; }

        int row0 = rt * 128, col0 = ct * 128;
        const float* bias = Ball + (size_t)e * Nd;
        const __half* We = Wt + (size_t)e * Kd * Nd + col0;

        int wid = tid >> 5, lid = tid & 31;
        int g = lid >> 2, t = lid & 3;
        int wm = wid & 1, wn = wid >> 1;
        int m_base = wm * 64, n_base = wn * 32;

        int arow = tid >> 1, half = tid & 1;
        const __half* Ar;
        uint32_t asz = 16;
        if (LAYER == 1) {
            int slot = g_perm[row0 + arow];
            if (slot >= 0) Ar = Ain + (size_t)(slot >> 1) * Kd;
            else { Ar = Ain; asz = 0; }
        } else {
            Ar = Ain + (size_t)(row0 + arow) * Kd;
        }
        int wkrow = tid >> 3, wchunk = tid & 7;

        uint32_t sbase = smem_u32(smem);
        uint32_t afoff = (uint32_t)arow * AROWB + half * 32;
        uint32_t wfoff = AREG + (uint32_t)wkrow * WROWB + wchunk * 32;

        float acc[4][4][4];
#pragma unroll
        for (int mt = 0; mt < 4; mt++)
#pragma unroll
            for (int nt = 0; nt < 4; nt++)
#pragma unroll
                for (int q = 0; q < 4; q++) acc[mt][nt][q] = 0.f;

        constexpr int KC = Kd / 32;

        auto fill = [&](int kc) {
            uint32_t stg = sbase + (uint32_t)(kc & (NSTG - 1)) * STAGE;
            int k0 = kc * 32;
            const __half* sa = Ar + k0 + half * 16;
            CP16Z(stg + afoff, sa, asz); CP16Z(stg + afoff + 16, sa + 8, asz);
            const __half* sw = We + (size_t)(k0 + wkrow) * Nd + wchunk * 16;
            CP16(stg + wfoff, sw); CP16(stg + wfoff + 16, sw + 8);
        };

        fill(0); CP_COMMIT();
        fill(1); CP_COMMIT();
        fill(2); CP_COMMIT();

        uint32_t lrow = lid & 15;
        uint32_t lhalf16 = (lid >> 4) * 16;

        for (int kc = 0; kc < KC; kc++) {
            CP_WAIT2();
            __syncthreads();
            if (kc + 3 < KC) fill(kc + 3);
            CP_COMMIT();

            // conversion LOAD at iteration top (latency hidden by MMA block)
            float4 cv0, cv1;
            bool docvt = (LAYER < 3) && (cvt_pos < cvt_end);
            if (docvt) {
                cv0 = *(const float4*)(Wnext + cvt_pos);
                cv1 = *(const float4*)(Wnext + cvt_pos + 4);
            }

            uint32_t stg = sbase + (uint32_t)(kc & (NSTG - 1)) * STAGE;
#pragma unroll
            for (int ks = 0; ks < 2; ks++) {
                uint32_t ah[4][4];
                uint32_t koff = (uint32_t)ks * 32 + lhalf16;
#pragma unroll
                for (int mt = 0; mt < 4; mt++)
                    ldm_x4(ah[mt], stg + (uint32_t)(m_base + mt * 16 + lrow) * AROWB + koff);

                uint32_t b0[4], b1[4];
#pragma unroll
                for (int nn = 0; nn < 2; nn++) {
                    uint32_t r[4];
                    uint32_t addr = stg + AREG
                                  + (uint32_t)(ks * 16 + lrow) * WROWB
                                  + (uint32_t)(n_base + nn * 16) * 2 + lhalf16;
                    ldm_x4(r, addr);
                    b0[2 * nn]     = movm_t(r[0]);
                    b1[2 * nn]     = movm_t(r[1]);
                    b0[2 * nn + 1] = movm_t(r[2]);
                    b1[2 * nn + 1] = movm_t(r[3]);
                }
#pragma unroll
                for (int mt = 0; mt < 4; mt++)
#pragma unroll
                    for (int nt = 0; nt < 4; nt++)
                        mma16816(acc[mt][nt], ah[mt], b0[nt], b1[nt]);
            }

            // conversion STORE after the MMA block (data long since arrived)
            if (docvt) {
                cvt8_store(cv0, cv1, Wdst + cvt_pos);
                cvt_pos += 2048;
            }
        }

        // ---- epilogue ----
        __half* Oh = nullptr;
        if (LAYER == 1)      Oh = g_a1;
        else if (LAYER == 2) Oh = g_a2;

#pragma unroll
        for (int mt = 0; mt < 4; mt++) {
            int rA = row0 + m_base + mt * 16 + g;
#pragma unroll
            for (int nt = 0; nt < 4; nt++) {
                int col = col0 + n_base + nt * 8 + t * 2;
                float2 bv = *(const float2*)(bias + col);
                float2 o0, o1;
                o0.x = acc[mt][nt][0] + bv.x; o0.y = acc[mt][nt][1] + bv.y;
                o1.x = acc[mt][nt][2] + bv.x; o1.y = acc[mt][nt][3] + bv.y;
                if (LAYER < 3) {
                    o0.x = fmaxf(o0.x, 0.f); o0.y = fmaxf(o0.y, 0.f);
                    o1.x = fmaxf(o1.x, 0.f); o1.y = fmaxf(o1.y, 0.f);
                    __half2 h0 = __floats2half2_rn(o0.x, o0.y);
                    __half2 h1 = __floats2half2_rn(o1.x, o1.y);
                    *(uint32_t*)(Oh + (size_t)rA * Nd + col)       = *(uint32_t*)&h0;
                    *(uint32_t*)(Oh + (size_t)(rA + 8) * Nd + col) = *(uint32_t*)&h1;
                } else {
                    *(float2*)(g_or + (size_t)rA * Nd + col)       = o0;
                    *(float2*)(g_or + (size_t)(rA + 8) * Nd + col) = o1;
                }
            }
        }
    }

    // ---- drain any remaining conversion blocks (empty CTAs do all here) ----
    if (LAYER < 3) {
        while (cvt_pos < cvt_end) {
            cvt8(Wnext + cvt_pos, Wdst + cvt_pos);
            cvt_pos += 2048;
        }
    }
}

// ---------------- combine ----------------
__global__ void combine_k(float* __restrict__ out) {
    int t = blockIdx.x, c = threadIdx.x;
    int r0 = g_inv[t * 2], r1 = g_inv[t * 2 + 1];
    float w0 = g_gw[t * 2], w1 = g_gw[t * 2 + 1];
    const float4* a = (const float4*)(g_or + (size_t)r0 * DO_);
    const float4* b = (const float4*)(g_or + (size_t)r1 * DO_);
    float4 va = a[c], vb = b[c], o;
    o.x = w0 * va.x + w1 * vb.x;
    o.y = w0 * va.y + w1 * vb.y;
    o.z = w0 * va.z + w1 * vb.z;
    o.w = w0 * va.w + w1 * vb.w;
    ((float4*)(out + (size_t)t * DO_))[c] = o;
}

__global__ void idxout_k(float* __restrict__ dst, int n) {
    int i = blockIdx.x * blockDim.x + threadIdx.x;
    if (i < n) dst[i] = (float)g_idx[i];
}

// ---------------- launch ----------------
extern "C" void kernel_launch(void* const* d_in, const int* in_sizes, int n_in,
                              void* d_out, int out_size) {
    (void)in_sizes; (void)n_in;
    const float* xr = (const float*)d_in[0];
    const float* xe = (const float*)d_in[1];
    const float* Wg = (const float*)d_in[2];
    const float* bg = (const float*)d_in[3];
    const float* eb = (const float*)d_in[4];
    const float* W1 = (const float*)d_in[5];
    const float* b1 = (const float*)d_in[6];
    const float* W2 = (const float*)d_in[7];
    const float* b2 = (const float*)d_in[8];
    const float* W3 = (const float*)d_in[9];
    const float* b3 = (const float*)d_in[10];
    float* out = (float*)d_out;

    static cudaStream_t sB = 0;
    static cudaEvent_t evRoot = 0, ev_w1 = 0;
    if (sB == 0) {
        cudaStreamCreateWithFlags(&sB, cudaStreamNonBlocking);
        cudaEventCreateWithFlags(&evRoot, cudaEventDisableTiming);
        cudaEventCreateWithFlags(&ev_w1, cudaEventDisableTiming);
    }

    cudaFuncSetAttribute(mma_gemm_k<1, DI_, H1_>, cudaFuncAttributeMaxDynamicSharedMemorySize, SMEM_GEMM);
    cudaFuncSetAttribute(mma_gemm_k<2, H1_, H2_>, cudaFuncAttributeMaxDynamicSharedMemorySize, SMEM_GEMM);
    cudaFuncSetAttribute(mma_gemm_k<3, H2_, DO_>, cudaFuncAttributeMaxDynamicSharedMemorySize, SMEM_GEMM);

    // fork: wcvt1 overlaps the routing chain
    cudaEventRecord(evRoot, 0);
    cudaStreamWaitEvent(sB, evRoot, 0);
    wcvt1_k<<<(int)(((size_t)E_ * DI_ * H1_ / 8) / 256), 256, 0, sB>>>(W1);
    cudaEventRecord(ev_w1, sB);

    // origin: routing chain
    init_k<<<(MAXROWS_ + 255) / 256, 256>>>();
    router_k<<<B_, 256>>>(xr, Wg, bg, eb);
    xsplit_k<<<(B_ * DI_ / 4) / 256, 256>>>(xe);
    prefix_k<<<1, 1>>>();
    scatter_k<<<NS_ / 256, 256>>>();

    // join + GEMM chain; GEMM1 converts W2 inline, GEMM2 converts W3 inline
    cudaStreamWaitEvent(0, ev_w1, 0);
    mma_gemm_k<1, DI_, H1_><<<dim3(H1_ / 128, MAXTILES_), 256, SMEM_GEMM>>>(b1, W2);
    mma_gemm_k<2, H1_, H2_><<<dim3(H2_ / 128, MAXTILES_), 256, SMEM_GEMM>>>(b2, W3);
    mma_gemm_k<3, H2_, DO_><<<dim3(DO_ / 128, MAXTILES_), 256, SMEM_GEMM>>>(b3, nullptr);

    combine_k<<<B_, 256>>>(out);

    int tail = out_size - B_ * DO_;
    if (tail > 0) {
        int n = tail < NS_ ? tail : NS_;
        idxout_k<<<(n + 255) / 256, 256>>>(out + (size_t)B_ * DO_, n);
    }
}